// round 16
// baseline (speedup 1.0000x reference)
#include <cuda_runtime.h>
#include <cuda_fp16.h>
#include <cstdint>

#define NATOMS   32768
#define NBONDS   65536
#define NMESS    8192
#define HID      512
#define MAXNB    15
#define AFD      35
#define FBDIM    40
#define FBPAD    64
#define NMOLS    1024
#define KOPAD    576   // 512 (nei) + 35 (fatoms) + 29 pad, multiple of 64

#define ASCALE 0.00390625f   // 2^-8
#define DSCALE 256.0f        // 2^8

// -------- scratch (device globals; fp16 as uint4 arrays for 16B alignment) ------
__device__ uint4 g_binh  [(size_t)NBONDS * HID   / 8];   // fp16 binput (unscaled)
__device__ uint4 g_msgh0 [(size_t)NBONDS * HID   / 8];   // fp16 msg*2^-8 (ping)
__device__ uint4 g_msgh1 [(size_t)NBONDS * HID   / 8];   // fp16 msg*2^-8 (pong)
__device__ uint4 g_tmh   [(size_t)NMESS  * HID   / 8];   // fp16 tree_msg*2^-8
__device__ uint4 g_neih  [(size_t)NBONDS * HID   / 8];   // fp16 gather out (scaled)
__device__ uint4 g_fbh   [(size_t)NBONDS * FBPAD / 8];   // fp16 fbonds*2^-8, padded
__device__ uint4 g_ainh  [(size_t)NATOMS * KOPAD / 8];   // fp16 [nei|fatoms*s|0]
__device__ uint4 g_wiTh  [(size_t)HID * FBPAD / 8];      // fp16 W_i^T [n,k]
__device__ uint4 g_whTh  [(size_t)HID * HID   / 8];      // fp16 W_h^T [n,k]
__device__ uint4 g_woTh  [(size_t)HID * KOPAD / 8];      // fp16 W_o^T [n,k] reordered

// ======================= helpers =======================
__device__ __forceinline__ uint32_t smem_u32(const void* p) {
    uint32_t a;
    asm("{ .reg .u64 t; cvta.to.shared.u64 t, %1; cvt.u32.u64 %0, t; }" : "=r"(a) : "l"(p));
    return a;
}

__device__ __forceinline__ void cp_async16(uint32_t dst, const void* src) {
    asm volatile("cp.async.cg.shared.global [%0], [%1], 16;" :: "r"(dst), "l"(src));
}

__device__ __forceinline__ void mma_f16(float* c, unsigned a0, unsigned a1,
                                        unsigned a2, unsigned a3,
                                        unsigned b0, unsigned b1) {
    asm volatile(
        "mma.sync.aligned.m16n8k16.row.col.f32.f16.f16.f32 "
        "{%0,%1,%2,%3}, {%4,%5,%6,%7}, {%8,%9}, {%0,%1,%2,%3};"
        : "+f"(c[0]), "+f"(c[1]), "+f"(c[2]), "+f"(c[3])
        : "r"(a0), "r"(a1), "r"(a2), "r"(a3), "r"(b0), "r"(b1));
}

__device__ __forceinline__ void ldsm_x4(unsigned& r0, unsigned& r1,
                                        unsigned& r2, unsigned& r3, uint32_t addr) {
    asm volatile("ldmatrix.sync.aligned.m8n8.x4.shared.b16 {%0,%1,%2,%3}, [%4];"
                 : "=r"(r0), "=r"(r1), "=r"(r2), "=r"(r3) : "r"(addr));
}

// ======================= fp16 tensor-core GEMM, cp.async 3-stage ==================
// C-tile 128x128, BK=64, 256 threads (8 warps 4x2), warp tile 32x64.
// A [M,KA] fp16 row-major; B [N,KB] fp16 row-major (pre-transposed weights).
// tile_off: M-tile offset (row band = (blockIdx.y + tile_off)*128) for split-half
// dual-stream execution.
#define HS 36
#define HTILE_WORDS (128 * HS)               // 4608 u32 per tile
#define HGEMM_SMEM  (6 * HTILE_WORDS * 4)    // 110592 bytes (3 stages x A,B)

template<bool ADD_C, bool ADD_BIAS, bool HALF_OUT, bool PRE_HALF, bool SEG, int KC>
__global__ __launch_bounds__(256)
void hgemm(const __half* __restrict__ A, const __half* __restrict__ B,
           const __half* __restrict__ Cadd, const float* __restrict__ bias,
           __half* __restrict__ Dh, __half* __restrict__ Dpre,
           float* __restrict__ out, const int* __restrict__ scope, int tile_off)
{
    constexpr int K = KC * 64;
    extern __shared__ unsigned smem[];
    const uint32_t sb = smem_u32(smem);

    const int tid  = threadIdx.x;
    const int bn   = blockIdx.x;
    const int bmx  = blockIdx.y + tile_off;
    const int warp = tid >> 5, lane = tid & 31;
    const int wm = warp >> 1;            // 0..3  -> 32-row band
    const int wn = warp & 1;             // 0..1  -> 64-col band
    const int lrow = lane >> 2;          // 0..7
    const int lcol = lane & 3;           // 0..3

    const int l8m = lane >> 3;
    const int l8q = lane & 7;
    uint32_t a_off[2];
#pragma unroll
    for (int i = 0; i < 2; i++)
        a_off[i] = (uint32_t)(((wm * 32 + i * 16 + (l8m & 1) * 8 + l8q) * HS
                               + (l8m >> 1) * 4) * 4);
    uint32_t b_off[4];
#pragma unroll
    for (int p = 0; p < 4; p++)
        b_off[p] = (uint32_t)(((wn * 64 + (2 * p + (l8m >> 1)) * 8 + l8q) * HS
                               + (l8m & 1) * 4) * 4);

    float acc[2][8][4];
#pragma unroll
    for (int i = 0; i < 2; i++)
#pragma unroll
        for (int j = 0; j < 8; j++)
#pragma unroll
            for (int q = 0; q < 4; q++) acc[i][j][q] = 0.f;

    auto load_stage = [&](int s, int kt) {
#pragma unroll
        for (int i = 0; i < 4; i++) {
            const int idx = tid + i * 256;
            const int r = idx >> 3, c = idx & 7;
            cp_async16(sb + (uint32_t)((s * HTILE_WORDS + r * HS) * 4 + c * 16),
                       A + (size_t)(bmx * 128 + r) * K + kt * 64 + c * 8);
        }
#pragma unroll
        for (int i = 0; i < 4; i++) {
            const int idx = tid + i * 256;
            const int r = idx >> 3, c = idx & 7;
            cp_async16(sb + (uint32_t)(((3 + s) * HTILE_WORDS + r * HS) * 4 + c * 16),
                       B + (size_t)(bn * 128 + r) * K + kt * 64 + c * 8);
        }
    };

    load_stage(0, 0);
    asm volatile("cp.async.commit_group;" ::: "memory");
    if (KC > 1) load_stage(1, 1);
    asm volatile("cp.async.commit_group;" ::: "memory");

#pragma unroll 1
    for (int kt = 0; kt < KC; kt++) {
        if (kt < KC - 1)
            asm volatile("cp.async.wait_group 1;" ::: "memory");
        else
            asm volatile("cp.async.wait_group 0;" ::: "memory");
        __syncthreads();

        if (kt + 2 < KC) load_stage((kt + 2) % 3, kt + 2);
        asm volatile("cp.async.commit_group;" ::: "memory");

        const int s = kt % 3;
        const uint32_t sA = sb + (uint32_t)(s * HTILE_WORDS) * 4;
        const uint32_t sB = sb + (uint32_t)((3 + s) * HTILE_WORDS) * 4;
#pragma unroll
        for (int ks = 0; ks < 4; ks++) {
            const uint32_t kb = (uint32_t)(ks * 32);
            unsigned a[2][4];
#pragma unroll
            for (int i = 0; i < 2; i++)
                ldsm_x4(a[i][0], a[i][1], a[i][2], a[i][3], sA + a_off[i] + kb);
#pragma unroll
            for (int p = 0; p < 4; p++) {
                unsigned b0, b1, b2, b3;
                ldsm_x4(b0, b1, b2, b3, sB + b_off[p] + kb);
#pragma unroll
                for (int i = 0; i < 2; i++) {
                    mma_f16(acc[i][2 * p],     a[i][0], a[i][1], a[i][2], a[i][3], b0, b1);
                    mma_f16(acc[i][2 * p + 1], a[i][0], a[i][1], a[i][2], a[i][3], b2, b3);
                }
            }
        }
    }

    // -------- epilogue --------
    if (SEG) {
        float2 sj[8];
#pragma unroll
        for (int j = 0; j < 8; j++) sj[j] = make_float2(0.f, 0.f);
#pragma unroll
        for (int i = 0; i < 2; i++)
#pragma unroll
            for (int j = 0; j < 8; j++) {
                const int c = bn * 128 + wn * 64 + j * 8 + lcol * 2;
#pragma unroll
                for (int h = 0; h < 2; h++) {
                    float2 v = make_float2(acc[i][j][h * 2] * DSCALE,
                                           acc[i][j][h * 2 + 1] * DSCALE);
                    if (ADD_BIAS) { v.x += bias[c]; v.y += bias[c + 1]; }
                    v.x = fmaxf(v.x, 0.f); v.y = fmaxf(v.y, 0.f);
                    sj[j].x += v.x; sj[j].y += v.y;
                }
            }
        const int mol = bmx * 4 + wm;
        const float inv = 1.f / (float)scope[mol * 2 + 1];
#pragma unroll
        for (int j = 0; j < 8; j++) {
            float2 s = sj[j];
#pragma unroll
            for (int mask = 4; mask <= 16; mask <<= 1) {
                s.x += __shfl_xor_sync(0xffffffffu, s.x, mask);
                s.y += __shfl_xor_sync(0xffffffffu, s.y, mask);
            }
            if (lane < 4) {
                const int c = bn * 128 + wn * 64 + j * 8 + lcol * 2;
                s.x *= inv; s.y *= inv;
                *(float2*)(out + (size_t)mol * HID + c) = s;
            }
        }
    } else {
#pragma unroll
        for (int i = 0; i < 2; i++) {
            const int r0 = bmx * 128 + wm * 32 + i * 16 + lrow;
#pragma unroll
            for (int j = 0; j < 8; j++) {
                const int c = bn * 128 + wn * 64 + j * 8 + lcol * 2;
#pragma unroll
                for (int h = 0; h < 2; h++) {
                    const size_t base = (size_t)(r0 + h * 8) * HID + c;
                    float2 v = make_float2(acc[i][j][h * 2] * DSCALE,
                                           acc[i][j][h * 2 + 1] * DSCALE);
                    if (ADD_C) {
                        float2 cf = __half22float2(*(const __half2*)(Cadd + base));
                        v.x += cf.x; v.y += cf.y;
                    }
                    if (ADD_BIAS) { v.x += bias[c]; v.y += bias[c + 1]; }
                    if (PRE_HALF)
                        *(__half2*)(Dpre + base) = __floats2half2_rn(v.x, v.y);
                    v.x = fmaxf(v.x, 0.f); v.y = fmaxf(v.y, 0.f);
                    if (HALF_OUT)
                        *(__half2*)(Dh + base) = __floats2half2_rn(v.x * ASCALE,
                                                                   v.y * ASCALE);
                }
            }
        }
    }
}

// ======================= gather-sum (scaled fp16 tables -> scaled fp16 out) ========
__global__ void gather_h_kernel(const int* __restrict__ graph,
                                const __half* __restrict__ tm,
                                const __half* __restrict__ gm,
                                __half* __restrict__ out, int ostride, int rowoff)
{
    const int row = blockIdx.x + rowoff;
    const int t = threadIdx.x;  // 128 threads, 4 cols each
    __shared__ int idx[MAXNB];
    if (t < MAXNB) idx[t] = graph[row * MAXNB + t];
    __syncthreads();

    float a0 = 0.f, a1 = 0.f, a2 = 0.f, a3 = 0.f;
#pragma unroll
    for (int j = 0; j < MAXNB; j++) {
        const int id = idx[j];
        const __half* src = (id < NMESS) ? (tm + (size_t)id * HID)
                                         : (gm + (size_t)(id - NMESS) * HID);
        uint2 r = *(const uint2*)(src + t * 4);
        float2 f0 = __half22float2(*reinterpret_cast<const __half2*>(&r.x));
        float2 f1 = __half22float2(*reinterpret_cast<const __half2*>(&r.y));
        a0 += f0.x; a1 += f0.y; a2 += f1.x; a3 += f1.y;
    }
    __half2 h0 = __floats2half2_rn(a0, a1);
    __half2 h1 = __floats2half2_rn(a2, a3);
    uint2 o = make_uint2(*reinterpret_cast<unsigned*>(&h0),
                         *reinterpret_cast<unsigned*>(&h1));
    *(uint2*)(out + (size_t)row * ostride + t * 4) = o;
}

// ======================= prep kernels =======================
__global__ void conv_tm_kernel(const float* __restrict__ tm, __half* __restrict__ tmh)
{
    const int i = blockIdx.x * blockDim.x + threadIdx.x;
    if (i < NMESS * HID) tmh[i] = __float2half(tm[i] * ASCALE);
}

__global__ void conv_fb_kernel(const float* __restrict__ fb, __half* __restrict__ fbh)
{
    const int i = blockIdx.x * blockDim.x + threadIdx.x;
    if (i >= NBONDS * FBPAD) return;
    const int r = i >> 6, c = i & (FBPAD - 1);
    fbh[i] = __float2half((c < FBDIM) ? fb[r * FBDIM + c] * ASCALE : 0.f);
}

__global__ void fill_ain_atoms_kernel(const float* __restrict__ fatoms,
                                      __half* __restrict__ ainh)
{
    const int i = blockIdx.x * blockDim.x + threadIdx.x;
    if (i >= NATOMS * (KOPAD - HID)) return;
    const int r = i / (KOPAD - HID), c = i - r * (KOPAD - HID);
    __half v = __float2half((c < AFD) ? fatoms[r * AFD + c] * ASCALE : 0.f);
    ainh[(size_t)r * KOPAD + HID + c] = v;
}

__global__ void trans_wi_kernel(const float* __restrict__ Wi, __half* __restrict__ wiT)
{
    const int i = blockIdx.x * blockDim.x + threadIdx.x;
    if (i >= HID * FBPAD) return;
    const int n = i >> 6, k = i & (FBPAD - 1);
    wiT[i] = __float2half((k < FBDIM) ? Wi[(size_t)k * HID + n] : 0.f);
}

__global__ void trans_wh_kernel(const float* __restrict__ Wh, __half* __restrict__ whT)
{
    const int i = blockIdx.x * blockDim.x + threadIdx.x;
    if (i >= HID * HID) return;
    const int n = i >> 9, k = i & (HID - 1);
    whT[i] = __float2half(Wh[(size_t)k * HID + n]);
}

__global__ void trans_wo_kernel(const float* __restrict__ Wo, __half* __restrict__ woT)
{
    const int i = blockIdx.x * blockDim.x + threadIdx.x;
    if (i >= HID * KOPAD) return;
    const int n = i / KOPAD, k = i - n * KOPAD;
    float v;
    if (k < HID)            v = Wo[(size_t)(AFD + k) * HID + n];
    else if (k < HID + AFD) v = Wo[(size_t)(k - HID) * HID + n];
    else                    v = 0.f;
    woT[i] = __float2half(v);
}

// ======================= launch =======================
extern "C" void kernel_launch(void* const* d_in, const int* in_sizes, int n_in,
                              void* d_out, int out_size)
{
    const float* fatoms = (const float*)d_in[0];
    const float* fbonds = (const float*)d_in[1];
    const int*   agraph = (const int*)  d_in[2];
    const int*   bgraph = (const int*)  d_in[3];
    const int*   scope  = (const int*)  d_in[4];
    const float* tm     = (const float*)d_in[5];
    const float* W_i    = (const float*)d_in[6];
    const float* W_h    = (const float*)d_in[7];
    const float* W_o    = (const float*)d_in[8];
    const float* b_o    = (const float*)d_in[9];
    float* out = (float*)d_out;

    void *p0, *p1, *p2, *p3, *p4, *p5, *p6, *p7, *p8, *p9;
    cudaGetSymbolAddress(&p0, g_msgh0);
    cudaGetSymbolAddress(&p1, g_msgh1);
    cudaGetSymbolAddress(&p2, g_tmh);
    cudaGetSymbolAddress(&p3, g_neih);
    cudaGetSymbolAddress(&p4, g_fbh);
    cudaGetSymbolAddress(&p5, g_ainh);
    cudaGetSymbolAddress(&p6, g_binh);
    cudaGetSymbolAddress(&p7, g_wiTh);
    cudaGetSymbolAddress(&p8, g_whTh);
    cudaGetSymbolAddress(&p9, g_woTh);
    __half* msgh0 = (__half*)p0;
    __half* msgh1 = (__half*)p1;
    __half* tmh   = (__half*)p2;
    __half* neih  = (__half*)p3;
    __half* fbh   = (__half*)p4;
    __half* ainh  = (__half*)p5;
    __half* binh  = (__half*)p6;
    __half* wiTh  = (__half*)p7;
    __half* whTh  = (__half*)p8;
    __half* woTh  = (__half*)p9;

    // side stream + events, created once on the (uncaptured) correctness call
    static cudaStream_t s2 = nullptr;
    static cudaEvent_t evs[16];
    if (s2 == nullptr) {
        cudaStreamCreateWithFlags(&s2, cudaStreamNonBlocking);
        for (int i = 0; i < 16; i++)
            cudaEventCreateWithFlags(&evs[i], cudaEventDisableTiming);
    }

    cudaFuncSetAttribute(hgemm<false, false, true, true, false, 1>,
                         cudaFuncAttributeMaxDynamicSharedMemorySize, HGEMM_SMEM);
    cudaFuncSetAttribute(hgemm<true, false, true, false, false, 8>,
                         cudaFuncAttributeMaxDynamicSharedMemorySize, HGEMM_SMEM);
    cudaFuncSetAttribute(hgemm<false, true, false, false, true, 9>,
                         cudaFuncAttributeMaxDynamicSharedMemorySize, HGEMM_SMEM);

    int ei = 0;
    auto fork_to_s2 = [&]() { cudaEventRecord(evs[ei], 0); cudaStreamWaitEvent(s2, evs[ei], 0); ei++; };
    auto join_to_s0 = [&]() { cudaEventRecord(evs[ei], s2); cudaStreamWaitEvent((cudaStream_t)0, evs[ei], 0); ei++; };

    // ---- prep: transposes on s2, conversions on s0 ----
    fork_to_s2();
    trans_wi_kernel<<<(HID * FBPAD + 255) / 256, 256, 0, s2>>>(W_i, wiTh);
    trans_wh_kernel<<<(HID * HID + 255) / 256, 256, 0, s2>>>(W_h, whTh);
    trans_wo_kernel<<<(HID * KOPAD + 255) / 256, 256, 0, s2>>>(W_o, woTh);
    conv_tm_kernel<<<(NMESS * HID + 255) / 256, 256>>>(tm, tmh);
    conv_fb_kernel<<<(NBONDS * FBPAD + 255) / 256, 256>>>(fbonds, fbh);
    fill_ain_atoms_kernel<<<(NATOMS * (KOPAD - HID) + 255) / 256, 256>>>(fatoms, ainh);
    join_to_s0();

    // ---- init GEMM (full, s0): binput + msg0 = fbonds @ W_i ----
    hgemm<false, false, true, true, false, 1><<<dim3(4, NBONDS / 128), 256, HGEMM_SMEM>>>(
        fbh, wiTh, nullptr, nullptr, msgh0, binh, nullptr, nullptr, 0);

    // ---- 5 message-passing iterations, split halves across s0/s2 ----
    constexpr int HB = NBONDS / 2;          // 32768 rows per half
    constexpr int HT = NBONDS / 128 / 2;    // 256 M-tiles per half
    __half* cur = msgh0;
    __half* nxt = msgh1;
    for (int d = 0; d < 5; d++) {
        // s0: gather half A
        gather_h_kernel<<<HB, 128>>>(bgraph, tmh, cur, neih, HID, 0);
        fork_to_s2();                        // s2 waits for gatherA (and all prior s0)
        // s2: gather half B (overlaps gemmA below)
        gather_h_kernel<<<HB, 128, 0, s2>>>(bgraph, tmh, cur, neih, HID, HB);
        // s0: GEMM half A
        hgemm<true, false, true, false, false, 8><<<dim3(4, HT), 256, HGEMM_SMEM>>>(
            neih, whTh, binh, nullptr, nxt, nullptr, nullptr, nullptr, 0);
        // s2: GEMM half B
        hgemm<true, false, true, false, false, 8><<<dim3(4, HT), 256, HGEMM_SMEM, s2>>>(
            neih, whTh, binh, nullptr, nxt, nullptr, nullptr, nullptr, HT);
        join_to_s0();                        // next iter needs nxt fully written
        __half* t = cur; cur = nxt; nxt = t;
    }

    // ---- atom-side: split gather into ain + final GEMM with fused mean ----
    constexpr int HA  = NATOMS / 2;          // 16384 rows per half
    constexpr int HTA = NATOMS / 128 / 2;    // 128 M-tiles per half
    gather_h_kernel<<<HA, 128>>>(agraph, tmh, cur, ainh, KOPAD, 0);
    fork_to_s2();
    gather_h_kernel<<<HA, 128, 0, s2>>>(agraph, tmh, cur, ainh, KOPAD, HA);
    hgemm<false, true, false, false, true, 9><<<dim3(4, HTA), 256, HGEMM_SMEM>>>(
        ainh, woTh, nullptr, b_o, nullptr, nullptr, out, scope, 0);
    hgemm<false, true, false, false, true, 9><<<dim3(4, HTA), 256, HGEMM_SMEM, s2>>>(
        ainh, woTh, nullptr, b_o, nullptr, nullptr, out, scope, HTA);
    join_to_s0();                            // capture must end joined on origin
}